// round 17
// baseline (speedup 1.0000x reference)
#include <cuda_runtime.h>
#include <cuda_fp16.h>
#include <cstdint>

#define NN 50000
#define EE 800000
#define E2T (EE + NN)
#define IN_F 128
#define ED_F 16
#define F1 128
#define HEADS 4
#define HID 32
#define OUTF 32
#define NEG_SLOPE 0.2f
#define FULL 0xffffffffu

// ---------------- scratch ----------------
__device__ __align__(16) __half g_h1h[(size_t)NN * F1];
__device__ __align__(16) float g_hr[(size_t)NN * F1];
__device__ __align__(16) __half g_h2h[(size_t)NN * OUTF];
__device__ __align__(16) float4 g_rec[(size_t)E2T * 2];   // 32B/edge: [aed1][aed2,src,_,_]
__device__ int      g_count[NN];
__device__ int      g_rowstart[NN];
__device__ int      g_cursor[NN];
__device__ int      g_total;
__device__ float    g_asrc1[NN * HEADS], g_adst1[NN * HEADS];
__device__ float    g_asrc2[NN], g_adst2[NN];
__device__ float    g_wae1[ED_F * HEADS];
__device__ float    g_wae2[ED_F];
__device__ float    g_emean[ED_F];
__device__ int      g_is64;

__device__ __forceinline__ void load_edge(const void* eidx, int e, int is64, int& se, int& de) {
    if (is64) {
        const long long* p = (const long long*)eidx;
        se = (int)p[e];
        de = (int)p[(size_t)EE + e];
    } else {
        const int* p = (const int*)eidx;
        se = p[e];
        de = p[EE + e];
    }
}

__device__ __forceinline__ unsigned long long fma2(unsigned long long a, unsigned long long b,
                                                   unsigned long long c) {
    unsigned long long d;
    asm("fma.rn.f32x2 %0, %1, %2, %3;" : "=l"(d) : "l"(a), "l"(b), "l"(c));
    return d;
}
__device__ __forceinline__ float pairsum(unsigned long long v) {
    float lo, hi;
    asm("mov.b64 {%0, %1}, %2;" : "=f"(lo), "=f"(hi) : "l"(v));
    return lo + hi;
}
__device__ __forceinline__ float4 gather_h4(const __half* p) {
    uint2 u = *reinterpret_cast<const uint2*>(p);
    __half2 a = *reinterpret_cast<__half2*>(&u.x);
    __half2 b = *reinterpret_cast<__half2*>(&u.y);
    float2 fa = __half22float2(a);
    float2 fb = __half22float2(b);
    return make_float4(fa.x, fa.y, fb.x, fb.y);
}

// ---------------- setup ----------------
__global__ void setup(const void* eidx,
                      const float* __restrict__ We1, const float* __restrict__ ae1,
                      const float* __restrict__ We2, const float* __restrict__ ae2) {
    int i = blockIdx.x * blockDim.x + threadIdx.x;
    if (i < NN) g_count[i] = 0;
    if (i < ED_F) g_emean[i] = 0.f;
    if (i == 0) g_total = 0;
    if (blockIdx.x == 0 && threadIdx.x < 32) {
        const int* p = (const int*)eidx;
        int lane = threadIdx.x;
        int allzero = 1;
        #pragma unroll
        for (int k = 0; k < 8; k++)
            if (p[2 * (lane * 8 + k) + 1] != 0) allzero = 0;
        unsigned vote = __ballot_sync(FULL, allzero);
        if (lane == 0) g_is64 = (vote == FULL) ? 1 : 0;
    }
    if (blockIdx.x == 1) {
        int t = threadIdx.x;
        if (t < ED_F * HEADS) {
            int d = t >> 2, h = t & 3;
            float s = 0.f;
            #pragma unroll
            for (int c = 0; c < HID; c++) s += We1[d * F1 + h * HID + c] * ae1[h * HID + c];
            g_wae1[t] = s;
        } else if (t < ED_F * HEADS + ED_F) {
            int d = t - ED_F * HEADS;
            float s = 0.f;
            #pragma unroll
            for (int c = 0; c < OUTF; c++) s += We2[d * OUTF + c] * ae2[c];
            g_wae2[d] = s;
        }
    }
}

// ---------------- CSR count ----------------
__global__ void count_edges(const void* __restrict__ eidx) {
    int base = 4 * (blockIdx.x * blockDim.x + threadIdx.x);
    int is64 = g_is64;
    #pragma unroll
    for (int i = 0; i < 4; i++) {
        int e = base + i;
        if (e < EE) {
            int de;
            if (is64) de = (int)((const long long*)eidx)[(size_t)EE + e];
            else      de = ((const int*)eidx)[EE + e];
            atomicAdd(&g_count[de], 1);
        }
    }
}

// ---------------- parallel segment assignment ----------------
__global__ void assign_rows() {
    __shared__ int sh[256];
    __shared__ int sbase;
    int tid = threadIdx.x;
    int n = blockIdx.x * 256 + tid;
    int deg = (n < NN) ? g_count[n] + 1 : 0;
    sh[tid] = deg;
    __syncthreads();
    #pragma unroll
    for (int o = 1; o < 256; o <<= 1) {
        int v = (tid >= o) ? sh[tid - o] : 0;
        __syncthreads();
        sh[tid] += v;
        __syncthreads();
    }
    int incl = sh[tid];
    if (tid == 255) sbase = atomicAdd(&g_total, incl);
    __syncthreads();
    if (n < NN) {
        int rs = sbase + incl - deg;
        g_rowstart[n] = rs;
        g_cursor[n] = rs + 1;
    }
}

// ---------------- edge dots + CSR scatter + emean ----------------
__global__ void edge_dots_scatter(const void* __restrict__ eidx, const float* __restrict__ ea) {
    __shared__ float4 swae1[ED_F];
    __shared__ float  swae2[ED_F];
    __shared__ float  s16[ED_F];
    if (threadIdx.x < ED_F) {
        swae1[threadIdx.x] = *reinterpret_cast<const float4*>(&g_wae1[threadIdx.x * HEADS]);
        swae2[threadIdx.x] = g_wae2[threadIdx.x];
        s16[threadIdx.x] = 0.f;
    }
    __syncthreads();
    int e = blockIdx.x * blockDim.x + threadIdx.x;
    float4 q[4];
    if (e < EE) {
        const float4* eav = reinterpret_cast<const float4*>(ea + (size_t)e * ED_F);
        #pragma unroll
        for (int i = 0; i < 4; i++) q[i] = eav[i];
        float a0 = 0.f, a1 = 0.f, a2 = 0.f, a3 = 0.f, a4 = 0.f;
        #pragma unroll
        for (int i = 0; i < 4; i++) {
            const float* v = &q[i].x;
            #pragma unroll
            for (int j = 0; j < 4; j++) {
                int d = i * 4 + j;
                float vv = v[j];
                float4 w = swae1[d];
                a0 += vv * w.x;
                a1 += vv * w.y;
                a2 += vv * w.z;
                a3 += vv * w.w;
                a4 += vv * swae2[d];
            }
        }
        int se, de;
        load_edge(eidx, e, g_is64, se, de);
        int pos = atomicAdd(&g_cursor[de], 1);
        __stcs(&g_rec[2 * (size_t)pos],     make_float4(a0, a1, a2, a3));
        __stcs(&g_rec[2 * (size_t)pos + 1], make_float4(a4, __int_as_float(se), 0.f, 0.f));
    } else {
        #pragma unroll
        for (int i = 0; i < 4; i++) q[i] = make_float4(0.f, 0.f, 0.f, 0.f);
    }
    #pragma unroll
    for (int o = 16; o; o >>= 1) {
        #pragma unroll
        for (int i = 0; i < 4; i++) {
            q[i].x += __shfl_xor_sync(FULL, q[i].x, o);
            q[i].y += __shfl_xor_sync(FULL, q[i].y, o);
            q[i].z += __shfl_xor_sync(FULL, q[i].z, o);
            q[i].w += __shfl_xor_sync(FULL, q[i].w, o);
        }
    }
    if ((threadIdx.x & 31) == 0) {
        #pragma unroll
        for (int i = 0; i < 4; i++) {
            atomicAdd(&s16[i * 4 + 0], q[i].x);
            atomicAdd(&s16[i * 4 + 1], q[i].y);
            atomicAdd(&s16[i * 4 + 2], q[i].z);
            atomicAdd(&s16[i * 4 + 3], q[i].w);
        }
    }
    __syncthreads();
    if (threadIdx.x < ED_F) atomicAdd(&g_emean[threadIdx.x], s16[threadIdx.x]);
}

// ---------------- self-loop fill ----------------
__global__ void selfloop_fill() {
    __shared__ float sl1s[HEADS];
    __shared__ float sl2s;
    int t = threadIdx.x;
    const float inv_e = 1.f / (float)EE;
    if (t < HEADS) {
        float s = 0.f;
        #pragma unroll
        for (int d = 0; d < ED_F; d++) s += g_emean[d] * inv_e * g_wae1[d * HEADS + t];
        sl1s[t] = s;
    } else if (t == HEADS) {
        float s = 0.f;
        #pragma unroll
        for (int d = 0; d < ED_F; d++) s += g_emean[d] * inv_e * g_wae2[d];
        sl2s = s;
    }
    __syncthreads();
    int n = blockIdx.x * blockDim.x + t;
    if (n >= NN) return;
    int j = g_rowstart[n];
    g_rec[2 * (size_t)j]     = make_float4(sl1s[0], sl1s[1], sl1s[2], sl1s[3]);
    g_rec[2 * (size_t)j + 1] = make_float4(sl2s, __int_as_float(n), 0.f, 0.f);
}

// ---------------- GEMM1 (FFMA2): h1(fp16) = x @ W1, fused coef1 ----------------
__global__ void gemm1(const float* __restrict__ A, const float* __restrict__ B,
                      const float* __restrict__ as1, const float* __restrict__ ad1) {
    __shared__ float As[64][IN_F + 4];
    __shared__ float Bst[32][IN_F + 2];
    int row0 = blockIdx.x * 64;
    int tx = threadIdx.x & 31;
    int ty = threadIdx.x >> 5;
    {
        const float4* A4 = reinterpret_cast<const float4*>(A);
        #pragma unroll
        for (int i = 0; i < 8; i++) {
            int idx = threadIdx.x + i * 256;
            int r = idx >> 5, c4 = idx & 31;
            int gr = row0 + r;
            float4 v = (gr < NN) ? A4[(size_t)gr * 32 + c4] : make_float4(0.f, 0.f, 0.f, 0.f);
            *reinterpret_cast<float4*>(&As[r][c4 * 4]) = v;
        }
    }
    for (int cb = 0; cb < HEADS; cb++) {
        __syncthreads();
        #pragma unroll
        for (int i = 0; i < 16; i++) {
            int idx = threadIdx.x + i * 256;
            int r = idx >> 5, c = idx & 31;
            Bst[c][r] = B[(size_t)r * F1 + cb * 32 + c];
        }
        __syncthreads();
        unsigned long long acc2[8];
        #pragma unroll
        for (int r = 0; r < 8; r++) acc2[r] = 0ull;
        #pragma unroll 4
        for (int k2 = 0; k2 < IN_F / 2; k2++) {
            unsigned long long bv = *reinterpret_cast<const unsigned long long*>(&Bst[tx][k2 * 2]);
            #pragma unroll
            for (int r = 0; r < 8; r++) {
                unsigned long long av =
                    *reinterpret_cast<const unsigned long long*>(&As[ty * 8 + r][k2 * 2]);
                acc2[r] = fma2(av, bv, acc2[r]);
            }
        }
        float asv = as1[cb * HID + tx];
        float adv = ad1[cb * HID + tx];
        #pragma unroll
        for (int r = 0; r < 8; r++) {
            float acc = pairsum(acc2[r]);
            int gr = row0 + ty * 8 + r;
            if (gr < NN) g_h1h[(size_t)gr * F1 + cb * 32 + tx] = __float2half_rn(acc);
            float sv = acc * asv;
            float dv = acc * adv;
            #pragma unroll
            for (int o = 16; o; o >>= 1) {
                sv += __shfl_xor_sync(FULL, sv, o);
                dv += __shfl_xor_sync(FULL, dv, o);
            }
            if (tx == 0 && gr < NN) {
                g_asrc1[gr * HEADS + cb] = sv;
                g_adst1[gr * HEADS + cb] = dv;
            }
        }
    }
}

// ---------------- aggregate layer 1 (masked 8-edge pipeline, fp16 gather) ----------------
__global__ void aggregate1(const float* __restrict__ b1) {
    int n = (blockIdx.x * blockDim.x + threadIdx.x) >> 5;
    if (n >= NN) return;
    int lane = threadIdx.x & 31;
    int beg = g_rowstart[n];
    int end = beg + g_count[n] + 1;
    int h4 = lane & 3;
    int hh = lane >> 3;
    float adst = g_adst1[n * HEADS + h4];
    float denp = 0.f;
    float4 acc = make_float4(0.f, 0.f, 0.f, 0.f);
    int j = beg;
    int m = min(8, end - j);
    int sKl = 0;
    if (lane < 8) {
        int jj = j + ((lane < m) ? lane : m - 1);
        sKl = __float_as_int(reinterpret_cast<const float2*>(&g_rec[2 * (size_t)jj + 1])->y);
    }
    while (j < end) {
        int jn = j + 8;
        int mn = (jn < end) ? (end - jn < 8 ? end - jn : 8) : 0;
        int sKl_next = 0;
        if (mn > 0 && lane < 8) {
            int jj = jn + ((lane < mn) ? lane : mn - 1);
            sKl_next = __float_as_int(
                reinterpret_cast<const float2*>(&g_rec[2 * (size_t)jj + 1])->y);
        }
        int k = lane >> 2;
        int kcl = (k < m) ? k : m - 1;
        int skm = __shfl_sync(FULL, sKl, kcl);
        float aed = ((const float*)&g_rec[2 * (size_t)(j + kcl)])[h4];
        float lg = g_asrc1[skm * HEADS + h4] + adst + aed;
        lg = (lg > 0.f) ? lg : NEG_SLOPE * lg;
        float ex = __expf(lg);
        if (k >= m) ex = 0.f;
        denp += ex;
        #pragma unroll
        for (int kk = 0; kk < 8; kk++) {
            if (kk < m) {   // m is warp-uniform
                int s = __shfl_sync(FULL, sKl, kk);
                float e = __shfl_sync(FULL, ex, kk * 4 + hh);
                float4 v = gather_h4(&g_h1h[(size_t)s * F1 + lane * 4]);
                acc.x += e * v.x;
                acc.y += e * v.y;
                acc.z += e * v.z;
                acc.w += e * v.w;
            }
        }
        sKl = sKl_next;
        m = mn;
        j = jn;
    }
    denp += __shfl_xor_sync(FULL, denp, 4);
    denp += __shfl_xor_sync(FULL, denp, 8);
    denp += __shfl_xor_sync(FULL, denp, 16);
    float den = __shfl_sync(FULL, denp, hh);
    float inv = 1.f / (den + 1e-16f);
    float4 bv = *reinterpret_cast<const float4*>(&b1[lane * 4]);
    float4 o;
    o.x = fmaxf(acc.x * inv + bv.x, 0.f);
    o.y = fmaxf(acc.y * inv + bv.y, 0.f);
    o.z = fmaxf(acc.z * inv + bv.z, 0.f);
    o.w = fmaxf(acc.w * inv + bv.w, 0.f);
    *reinterpret_cast<float4*>(&g_hr[(size_t)n * F1 + lane * 4]) = o;
}

// ---------------- GEMM2 (FFMA2): h2(fp16) = hr @ W2, fused coef2 ----------------
__global__ void gemm2(const float* __restrict__ B,
                      const float* __restrict__ as2, const float* __restrict__ ad2) {
    __shared__ float As[64][F1 + 4];
    __shared__ float Bst[32][F1 + 2];
    int row0 = blockIdx.x * 64;
    int tx = threadIdx.x & 31;
    int ty = threadIdx.x >> 5;
    {
        const float4* A4 = reinterpret_cast<const float4*>(g_hr);
        #pragma unroll
        for (int i = 0; i < 8; i++) {
            int idx = threadIdx.x + i * 256;
            int r = idx >> 5, c4 = idx & 31;
            int gr = row0 + r;
            float4 v = (gr < NN) ? A4[(size_t)gr * 32 + c4] : make_float4(0.f, 0.f, 0.f, 0.f);
            *reinterpret_cast<float4*>(&As[r][c4 * 4]) = v;
        }
    }
    #pragma unroll
    for (int i = 0; i < 16; i++) {
        int idx = threadIdx.x + i * 256;
        int r = idx >> 5, c = idx & 31;
        Bst[c][r] = B[(size_t)r * OUTF + c];
    }
    __syncthreads();
    unsigned long long acc2[8];
    #pragma unroll
    for (int r = 0; r < 8; r++) acc2[r] = 0ull;
    #pragma unroll 4
    for (int k2 = 0; k2 < F1 / 2; k2++) {
        unsigned long long bv = *reinterpret_cast<const unsigned long long*>(&Bst[tx][k2 * 2]);
        #pragma unroll
        for (int r = 0; r < 8; r++) {
            unsigned long long av =
                *reinterpret_cast<const unsigned long long*>(&As[ty * 8 + r][k2 * 2]);
            acc2[r] = fma2(av, bv, acc2[r]);
        }
    }
    float asv = as2[tx];
    float adv = ad2[tx];
    #pragma unroll
    for (int r = 0; r < 8; r++) {
        float acc = pairsum(acc2[r]);
        int gr = row0 + ty * 8 + r;
        if (gr < NN) g_h2h[(size_t)gr * OUTF + tx] = __float2half_rn(acc);
        float sv = acc * asv;
        float dv = acc * adv;
        #pragma unroll
        for (int o = 16; o; o >>= 1) {
            sv += __shfl_xor_sync(FULL, sv, o);
            dv += __shfl_xor_sync(FULL, dv, o);
        }
        if (tx == 0 && gr < NN) {
            g_asrc2[gr] = sv;
            g_adst2[gr] = dv;
        }
    }
}

// ---------------- aggregate layer 2 (masked 8-edge pipeline, fp16 gather) ----------------
__global__ void aggregate2(float* __restrict__ out, const float* __restrict__ b2) {
    int n = (blockIdx.x * blockDim.x + threadIdx.x) >> 5;
    if (n >= NN) return;
    int lane = threadIdx.x & 31;
    int beg = g_rowstart[n];
    int end = beg + g_count[n] + 1;
    float adst = g_adst2[n];
    float denp = 0.f, acc = 0.f;
    int j = beg;
    int m = min(8, end - j);
    float2 sb = make_float2(0.f, 0.f);
    if (lane < 8) {
        int jj = j + ((lane < m) ? lane : m - 1);
        sb = *reinterpret_cast<const float2*>(&g_rec[2 * (size_t)jj + 1]);
    }
    while (j < end) {
        int jn = j + 8;
        int mn = (jn < end) ? (end - jn < 8 ? end - jn : 8) : 0;
        float2 sb_next = make_float2(0.f, 0.f);
        if (mn > 0 && lane < 8) {
            int jj = jn + ((lane < mn) ? lane : mn - 1);
            sb_next = *reinterpret_cast<const float2*>(&g_rec[2 * (size_t)jj + 1]);
        }
        int sK = __float_as_int(sb.y);
        float ex = 0.f;
        if (lane < 8) {
            float lg = g_asrc2[sK] + adst + sb.x;
            lg = (lg > 0.f) ? lg : NEG_SLOPE * lg;
            ex = __expf(lg);
            if (lane >= m) ex = 0.f;
            denp += ex;
        }
        #pragma unroll
        for (int kk = 0; kk < 8; kk++) {
            if (kk < m) {
                int s = __shfl_sync(FULL, sK, kk);
                float e = __shfl_sync(FULL, ex, kk);
                acc += e * __half2float(g_h2h[(size_t)s * OUTF + lane]);
            }
        }
        sb = sb_next;
        m = mn;
        j = jn;
    }
    denp += __shfl_xor_sync(FULL, denp, 1);
    denp += __shfl_xor_sync(FULL, denp, 2);
    denp += __shfl_xor_sync(FULL, denp, 4);
    denp += __shfl_xor_sync(FULL, denp, 8);
    denp += __shfl_xor_sync(FULL, denp, 16);
    out[(size_t)n * OUTF + lane] = acc / (denp + 1e-16f) + b2[lane];
}

// ---------------- launch ----------------
extern "C" void kernel_launch(void* const* d_in, const int* in_sizes, int n_in,
                              void* d_out, int out_size) {
    int used[64];
    for (int i = 0; i < n_in && i < 64; i++) used[i] = 0;
    auto take = [&](int want) -> const void* {
        for (int i = 0; i < n_in && i < 64; i++)
            if (!used[i] && in_sizes[i] == want) { used[i] = 1; return d_in[i]; }
        return nullptr;
    };
    const float* x   = (const float*)take(NN * IN_F);
    const void*  eix = take(2 * EE);
    const float* ea  = (const float*)take(EE * ED_F);
    const float* W1  = (const float*)take(IN_F * F1);
    const float* We1 = (const float*)take(ED_F * F1);
    const float* W2  = (const float*)take(F1 * OUTF);
    const float* We2 = (const float*)take(ED_F * OUTF);
    const float* g128[4] = {nullptr, nullptr, nullptr, nullptr};
    const float* g32[4]  = {nullptr, nullptr, nullptr, nullptr};
    int n128 = 0, n32 = 0;
    for (int i = 0; i < n_in && i < 64; i++) {
        if (used[i]) continue;
        if (in_sizes[i] == 128 && n128 < 4) g128[n128++] = (const float*)d_in[i];
        else if (in_sizes[i] == 32 && n32 < 4) g32[n32++] = (const float*)d_in[i];
    }
    const float* as1 = g128[0], *ad1 = g128[1], *ae1 = g128[2], *b1 = g128[3];
    const float* as2 = g32[0],  *ad2 = g32[1],  *ae2 = g32[2],  *b2 = g32[3];
    if (!x || !eix || !ea || !W1 || !We1 || !W2 || !We2 || n128 < 4 || n32 < 4) {
        x   = (const float*)d_in[0];  eix = d_in[1];               ea  = (const float*)d_in[2];
        W1  = (const float*)d_in[3];  We1 = (const float*)d_in[4];
        as1 = (const float*)d_in[5];  ad1 = (const float*)d_in[6]; ae1 = (const float*)d_in[7];
        b1  = (const float*)d_in[8];  W2  = (const float*)d_in[9]; We2 = (const float*)d_in[10];
        as2 = (const float*)d_in[11]; ad2 = (const float*)d_in[12]; ae2 = (const float*)d_in[13];
        b2  = (const float*)d_in[14];
    }
    float* out = (float*)d_out;

    const int TB = 256;

    static cudaStream_t s2 = nullptr;
    static cudaEvent_t e1 = nullptr, e2 = nullptr;
    if (!s2) {
        cudaStreamCreateWithFlags(&s2, cudaStreamNonBlocking);
        cudaEventCreateWithFlags(&e1, cudaEventDisableTiming);
        cudaEventCreateWithFlags(&e2, cudaEventDisableTiming);
    }

    cudaEventRecord(e1, 0);
    cudaStreamWaitEvent(s2, e1, 0);
    gemm1<<<(NN + 63) / 64, TB, 0, s2>>>(x, W1, as1, ad1);
    cudaEventRecord(e2, s2);

    setup<<<(NN + TB - 1) / TB, TB>>>(eix, We1, ae1, We2, ae2);
    count_edges<<<(EE + TB * 4 - 1) / (TB * 4), TB>>>(eix);
    assign_rows<<<(NN + TB - 1) / TB, TB>>>();
    edge_dots_scatter<<<(EE + TB - 1) / TB, TB>>>(eix, ea);
    selfloop_fill<<<(NN + TB - 1) / TB, TB>>>();

    cudaStreamWaitEvent(0, e2, 0);

    aggregate1<<<(int)(((size_t)NN * 32 + TB - 1) / TB), TB>>>(b1);
    gemm2<<<(NN + 63) / 64, TB>>>(W2, as2, ad2);
    aggregate2<<<(int)(((size_t)NN * 32 + TB - 1) / TB), TB>>>(out, b2);
}